// round 2
// baseline (speedup 1.0000x reference)
#include <cuda_runtime.h>
#include <math_constants.h>

// Problem shape (fixed by the dataset; runtime sizes checked against these caps)
#define MAXN 100000
#define MAXE 1200000
#define D    64

// Scratch (static device globals; allocation inside kernel_launch is forbidden)
__device__ float    g_y[(size_t)MAXN * 2 * D];   // y[(node*2+type)*64 + d]
__device__ int      g_cnt[MAXN];                 // in-degree per node
__device__ int      g_start[MAXN];               // CSR row start
__device__ int      g_cursor[MAXN];              // placement cursors
__device__ unsigned g_edata[MAXE];               // per-edge packed (src*2 + type)
__device__ int      g_bsum[256];                 // scan block sums

// ---------------------------------------------------------------------------
// 1) zero the histogram (runs every replay — the graph is captured once)
__global__ void zero_cnt_kernel(int n) {
    int i = blockIdx.x * blockDim.x + threadIdx.x;
    if (i < n) g_cnt[i] = 0;
}

// ---------------------------------------------------------------------------
// 2) node-level GEMM: y[n][t][:] = x[n] @ W[t] + b[t], t in {0,1}
//    128 threads: tid -> (type = tid>>6, d = tid&63); W column in 64 regs.
//    4 node-rows staged interleaved in shared: one LDS.128 feeds 4 FFMAs.
__global__ void gemm_kernel(const float* __restrict__ x,
                            const float* __restrict__ W,
                            const float* __restrict__ b, int n) {
    const int tid  = threadIdx.x;       // 0..127
    const int type = tid >> 6;
    const int d    = tid & 63;

    float w[D];
#pragma unroll
    for (int k = 0; k < D; k++) w[k] = W[type * D * D + k * D + d];
    const float bias = b[type * D + d];

    __shared__ float4 xs[D];            // xs[k] = {x0[k], x1[k], x2[k], x3[k]}
    float* xsf = (float*)xs;

    const int ngroups = n >> 2;
    for (int g = blockIdx.x; g < ngroups; g += gridDim.x) {
        const float* xg = x + (size_t)g * 4 * D;
        for (int i = tid; i < 4 * D; i += blockDim.x) {
            int k = i >> 2, j = i & 3;
            xsf[i] = xg[j * D + k];
        }
        __syncthreads();

        float a0 = bias, a1 = bias, a2 = bias, a3 = bias;
#pragma unroll
        for (int k = 0; k < D; k++) {
            float4 xk = xs[k];
            a0 = fmaf(xk.x, w[k], a0);
            a1 = fmaf(xk.y, w[k], a1);
            a2 = fmaf(xk.z, w[k], a2);
            a3 = fmaf(xk.w, w[k], a3);
        }
        size_t base = ((size_t)g * 8 + type) * D + d;   // node g*4, row stride 2*D
        g_y[base        ] = a0;
        g_y[base + 2 * D] = a1;
        g_y[base + 4 * D] = a2;
        g_y[base + 6 * D] = a3;
        __syncthreads();
    }

    if (blockIdx.x == 0) {              // tail nodes (n % 4)
        for (int node = ngroups * 4; node < n; node++) {
            float acc = bias;
            const float* xr = x + (size_t)node * D;
#pragma unroll
            for (int k = 0; k < D; k++) acc = fmaf(xr[k], w[k], acc);
            g_y[((size_t)node * 2 + type) * D + d] = acc;
        }
    }
}

// ---------------------------------------------------------------------------
// 3) histogram of dst  (edge_index is int32: JAX x64 is disabled by default)
__global__ void hist_kernel(const int* __restrict__ ei, int e, int n) {
    int i = blockIdx.x * blockDim.x + threadIdx.x;
    if (i < e) {
        int dn = ei[e + i];                       // dst row
        if ((unsigned)dn < (unsigned)n)           // guard: wrong dtype -> rel_err, not crash
            atomicAdd(&g_cnt[dn], 1);
    }
}

// ---------------------------------------------------------------------------
// 4a) per-block inclusive scan (1024/block) -> block-exclusive + block sum
__global__ void scan1_kernel(int n) {
    __shared__ int s[1024];
    int tid = threadIdx.x;
    int i = blockIdx.x * 1024 + tid;
    int v = (i < n) ? g_cnt[i] : 0;
    s[tid] = v;
    __syncthreads();
#pragma unroll
    for (int off = 1; off < 1024; off <<= 1) {
        int t = (tid >= off) ? s[tid - off] : 0;
        __syncthreads();
        s[tid] += t;
        __syncthreads();
    }
    if (i < n) g_start[i] = s[tid] - v;
    if (tid == 1023) g_bsum[blockIdx.x] = s[1023];
}

// 4b) scan block sums (nb <= 256) -> exclusive
__global__ void scan2_kernel(int nb) {
    __shared__ int s[256];
    int tid = threadIdx.x;
    int v = (tid < nb) ? g_bsum[tid] : 0;
    s[tid] = v;
    __syncthreads();
#pragma unroll
    for (int off = 1; off < 256; off <<= 1) {
        int t = (tid >= off) ? s[tid - off] : 0;
        __syncthreads();
        s[tid] += t;
        __syncthreads();
    }
    if (tid < nb) g_bsum[tid] = s[tid] - v;
}

// 4c) add block offsets, init cursors
__global__ void scan3_kernel(int n) {
    int i = blockIdx.x * blockDim.x + threadIdx.x;
    if (i < n) {
        int v = g_start[i] + g_bsum[i >> 10];
        g_start[i]  = v;
        g_cursor[i] = v;
    }
}

// ---------------------------------------------------------------------------
// 5) placement: edata[pos] = src*2 + type (direct row index into g_y)
__global__ void place_kernel(const int* __restrict__ ei,
                             const int* __restrict__ attr, int e, int n) {
    int i = blockIdx.x * blockDim.x + threadIdx.x;
    if (i < e) {
        int s  = ei[i];
        int dn = ei[e + i];
        int t  = attr[i] & 1;
        if ((unsigned)s < (unsigned)n && (unsigned)dn < (unsigned)n) {
            int pos = atomicAdd(&g_cursor[dn], 1);
            if ((unsigned)pos < (unsigned)MAXE)
                g_edata[pos] = (unsigned)((s << 1) | t);
        }
    }
}

// ---------------------------------------------------------------------------
// 6) aggregation: one warp per node; lane l owns dims {2l, 2l+1}.
//    Edge chunk loaded coalesced, broadcast via shuffle; rows gathered as
//    float2 from L2-resident g_y; max in registers — no output atomics.
__global__ void agg_kernel(float* __restrict__ out, int n) {
    int gt   = blockIdx.x * blockDim.x + threadIdx.x;
    int node = gt >> 5;
    int lane = gt & 31;
    if (node >= n) return;

    int c = g_cnt[node];
    int s = g_start[node];

    float vx = -CUDART_INF_F, vy = -CUDART_INF_F;
    for (int base = 0; base < c; base += 32) {
        int m = min(32, c - base);
        unsigned u = (lane < m) ? g_edata[s + base + lane] : 0u;
        for (int j = 0; j < m; j++) {
            unsigned uu = __shfl_sync(0xffffffffu, u, j);
            const float2* row = (const float2*)(g_y + (size_t)uu * D);
            float2 v = row[lane];
            vx = fmaxf(vx, v.x);
            vy = fmaxf(vy, v.y);
        }
    }
    if (c == 0) { vx = 0.f; vy = 0.f; }   // isolated nodes -> 0 per reference
    float2 o; o.x = vx; o.y = vy;
    ((float2*)out)[(size_t)node * 32 + lane] = o;
}

// ---------------------------------------------------------------------------
extern "C" void kernel_launch(void* const* d_in, const int* in_sizes, int n_in,
                              void* d_out, int out_size) {
    const float* x    = (const float*)d_in[0];   // [N,64]  f32
    const float* W    = (const float*)d_in[1];   // [2,64,64] f32
    const float* b    = (const float*)d_in[2];   // [2,64]  f32
    const int*   ei   = (const int*)d_in[3];     // [2,E]   i32 (JAX default x64-off)
    const int*   attr = (const int*)d_in[4];     // [E]     i32
    float*       out  = (float*)d_out;           // [N,64]  f32

    int n = in_sizes[0] / D;
    int e = in_sizes[4];
    if (n > MAXN) n = MAXN;
    if (e > MAXE) e = MAXE;

    zero_cnt_kernel<<<(n + 255) / 256, 256>>>(n);
    gemm_kernel<<<1024, 128>>>(x, W, b, n);
    hist_kernel<<<(e + 255) / 256, 256>>>(ei, e, n);

    int nb = (n + 1023) / 1024;
    scan1_kernel<<<nb, 1024>>>(n);
    scan2_kernel<<<1, 256>>>(nb);
    scan3_kernel<<<(n + 255) / 256, 256>>>(n);

    place_kernel<<<(e + 255) / 256, 256>>>(ei, attr, e, n);
    agg_kernel<<<(n * 32 + 255) / 256, 256>>>(out, n);
}

// round 3
// speedup vs baseline: 1.4842x; 1.4842x over previous
#include <cuda_runtime.h>
#include <math_constants.h>

#define MAXN 100000
#define MAXE 1200000
#define D    64
#define GN   16      // nodes per gemm group

__device__ float    g_y[(size_t)MAXN * 2 * D];   // y[(node*2+type)*64 + d]
__device__ int      g_cnt[MAXN];
__device__ int      g_start[MAXN];
__device__ int      g_cursor[MAXN];
__device__ unsigned g_edata[MAXE];               // packed (src*2 + type)
__device__ int      g_bsum[256];

// packed f32x2 helpers ------------------------------------------------------
__device__ __forceinline__ unsigned long long pack2(float lo, float hi) {
    unsigned long long r;
    asm("mov.b64 %0, {%1, %2};" : "=l"(r) : "r"(__float_as_uint(lo)), "r"(__float_as_uint(hi)));
    return r;
}
__device__ __forceinline__ void fma2(unsigned long long& a,
                                     unsigned long long x, unsigned long long w) {
    asm("fma.rn.f32x2 %0, %1, %2, %0;" : "+l"(a) : "l"(x), "l"(w));
}
__device__ __forceinline__ float2 unpack2(unsigned long long v) {
    unsigned lo, hi;
    asm("mov.b64 {%0, %1}, %2;" : "=r"(lo), "=r"(hi) : "l"(v));
    float2 f; f.x = __uint_as_float(lo); f.y = __uint_as_float(hi);
    return f;
}

// ---------------------------------------------------------------------------
__global__ void zero_cnt_kernel(int n) {
    int i = blockIdx.x * blockDim.x + threadIdx.x;
    if (i < n) g_cnt[i] = 0;
}

// ---------------------------------------------------------------------------
// GEMM: y[n][t][:] = x[n] @ W[t] + b[t].  128 threads: (type = tid>>6, d = tid&63).
// W column in 64 regs. 16 nodes/group; x staged transposed (xs[k*16+j]) so
// FMA-loop operand loads are broadcast LDS.128. Packed fma.rn.f32x2: 2 FMAs/instr.
__global__ void gemm_kernel(const float* __restrict__ x,
                            const float* __restrict__ W,
                            const float* __restrict__ b, int n) {
    const int tid  = threadIdx.x;
    const int type = tid >> 6;
    const int d    = tid & 63;

    float w[D];
#pragma unroll
    for (int k = 0; k < D; k++) w[k] = W[type * D * D + k * D + d];
    const float bias = b[type * D + d];
    const unsigned long long bb = pack2(bias, bias);

    __shared__ float xs[GN * D];                     // xs[k*16 + j] = x[node_j][k]
    const ulonglong2* xv = (const ulonglong2*)xs;    // 2 packed pairs per LDS.128

    const int ngroups = n / GN;
    for (int g = blockIdx.x; g < ngroups; g += gridDim.x) {
        const float* xg = x + (size_t)g * GN * D;
        for (int i = tid; i < GN * D; i += 128) {
            int k = i >> 4, j = i & 15;
            xs[i] = xg[j * D + k];
        }
        __syncthreads();

        unsigned long long acc[8];
#pragma unroll
        for (int q = 0; q < 8; q++) acc[q] = bb;

#pragma unroll
        for (int k = 0; k < D; k++) {
            unsigned long long ww = pack2(w[k], w[k]);
            ulonglong2 p0 = xv[k * 4 + 0];
            ulonglong2 p1 = xv[k * 4 + 1];
            ulonglong2 p2 = xv[k * 4 + 2];
            ulonglong2 p3 = xv[k * 4 + 3];
            fma2(acc[0], p0.x, ww); fma2(acc[1], p0.y, ww);
            fma2(acc[2], p1.x, ww); fma2(acc[3], p1.y, ww);
            fma2(acc[4], p2.x, ww); fma2(acc[5], p2.y, ww);
            fma2(acc[6], p3.x, ww); fma2(acc[7], p3.y, ww);
        }

#pragma unroll
        for (int q = 0; q < 8; q++) {
            float2 v = unpack2(acc[q]);
            size_t node0 = (size_t)g * GN + 2 * q;
            g_y[(node0 * 2 + type) * D + d]       = v.x;
            g_y[((node0 + 1) * 2 + type) * D + d] = v.y;
        }
        __syncthreads();
    }

    if (blockIdx.x == 0) {                           // tail (n % 16)
        for (int node = ngroups * GN; node < n; node++) {
            float acc = bias;
            const float* xr = x + (size_t)node * D;
#pragma unroll
            for (int k = 0; k < D; k++) acc = fmaf(xr[k], w[k], acc);
            g_y[((size_t)node * 2 + type) * D + d] = acc;
        }
    }
}

// ---------------------------------------------------------------------------
// histogram of dst, 4 edges/thread (int4)
__global__ void hist_kernel(const int* __restrict__ ei, int e, int n) {
    int t = blockIdx.x * blockDim.x + threadIdx.x;
    int base = t * 4;
    if (base + 4 <= e) {
        int4 d4 = *(const int4*)(ei + e + base);
        if ((unsigned)d4.x < (unsigned)n) atomicAdd(&g_cnt[d4.x], 1);
        if ((unsigned)d4.y < (unsigned)n) atomicAdd(&g_cnt[d4.y], 1);
        if ((unsigned)d4.z < (unsigned)n) atomicAdd(&g_cnt[d4.z], 1);
        if ((unsigned)d4.w < (unsigned)n) atomicAdd(&g_cnt[d4.w], 1);
    } else {
        for (int i = base; i < e; i++) {
            int dn = ei[e + i];
            if ((unsigned)dn < (unsigned)n) atomicAdd(&g_cnt[dn], 1);
        }
    }
}

// ---------------------------------------------------------------------------
// shuffle-based scans
__global__ void scan1_kernel(int n) {
    __shared__ int wsum[32];
    int tid = threadIdx.x, lane = tid & 31, wid = tid >> 5;
    int i = blockIdx.x * 1024 + tid;
    int v = (i < n) ? g_cnt[i] : 0;
    int inc = v;
#pragma unroll
    for (int off = 1; off < 32; off <<= 1) {
        int t = __shfl_up_sync(0xffffffffu, inc, off);
        if (lane >= off) inc += t;
    }
    if (lane == 31) wsum[wid] = inc;
    __syncthreads();
    if (wid == 0) {
        int s = wsum[lane];
#pragma unroll
        for (int off = 1; off < 32; off <<= 1) {
            int t = __shfl_up_sync(0xffffffffu, s, off);
            if (lane >= off) s += t;
        }
        wsum[lane] = s;
    }
    __syncthreads();
    int woff = (wid > 0) ? wsum[wid - 1] : 0;
    if (i < n) g_start[i] = woff + inc - v;          // exclusive
    if (tid == 1023) g_bsum[blockIdx.x] = wsum[31];  // block total
}

__global__ void scan2_kernel(int nb) {
    __shared__ int ws[8];
    int tid = threadIdx.x, lane = tid & 31, wid = tid >> 5;
    int v = (tid < nb) ? g_bsum[tid] : 0;
    int inc = v;
#pragma unroll
    for (int off = 1; off < 32; off <<= 1) {
        int t = __shfl_up_sync(0xffffffffu, inc, off);
        if (lane >= off) inc += t;
    }
    if (lane == 31) ws[wid] = inc;
    __syncthreads();
    if (wid == 0) {
        int s = (lane < 8) ? ws[lane] : 0;
#pragma unroll
        for (int off = 1; off < 8; off <<= 1) {
            int t = __shfl_up_sync(0xffffffffu, s, off);
            if (lane >= off) s += t;
        }
        if (lane < 8) ws[lane] = s;
    }
    __syncthreads();
    int woff = (wid > 0) ? ws[wid - 1] : 0;
    if (tid < nb) g_bsum[tid] = woff + inc - v;      // exclusive
}

__global__ void scan3_kernel(int n) {
    int i = blockIdx.x * blockDim.x + threadIdx.x;
    if (i < n) {
        int v = g_start[i] + g_bsum[i >> 10];
        g_start[i]  = v;
        g_cursor[i] = v;
    }
}

// ---------------------------------------------------------------------------
// placement, 4 edges/thread (int4 on src / dst / attr)
__global__ void place_kernel(const int* __restrict__ ei,
                             const int* __restrict__ attr, int e, int n) {
    int t = blockIdx.x * blockDim.x + threadIdx.x;
    int base = t * 4;
    if (base + 4 <= e) {
        int4 s4 = *(const int4*)(ei + base);
        int4 d4 = *(const int4*)(ei + e + base);
        int4 a4 = *(const int4*)(attr + base);
        int ss[4] = {s4.x, s4.y, s4.z, s4.w};
        int dd[4] = {d4.x, d4.y, d4.z, d4.w};
        int aa[4] = {a4.x, a4.y, a4.z, a4.w};
#pragma unroll
        for (int q = 0; q < 4; q++) {
            if ((unsigned)ss[q] < (unsigned)n && (unsigned)dd[q] < (unsigned)n) {
                int pos = atomicAdd(&g_cursor[dd[q]], 1);
                if ((unsigned)pos < (unsigned)MAXE)
                    g_edata[pos] = (unsigned)((ss[q] << 1) | (aa[q] & 1));
            }
        }
    } else {
        for (int i = base; i < e; i++) {
            int s = ei[i], dn = ei[e + i], a = attr[i] & 1;
            if ((unsigned)s < (unsigned)n && (unsigned)dn < (unsigned)n) {
                int pos = atomicAdd(&g_cursor[dn], 1);
                if ((unsigned)pos < (unsigned)MAXE)
                    g_edata[pos] = (unsigned)((s << 1) | a);
            }
        }
    }
}

// ---------------------------------------------------------------------------
// aggregation: warp/node, lane owns dims {2l,2l+1}; inner gather unrolled x4 (MLP=4)
__global__ void agg_kernel(float* __restrict__ out, int n) {
    int gt   = blockIdx.x * blockDim.x + threadIdx.x;
    int node = gt >> 5;
    int lane = gt & 31;
    if (node >= n) return;

    int c = g_cnt[node];
    int s = g_start[node];

    float vx = -CUDART_INF_F, vy = -CUDART_INF_F;
    for (int base = 0; base < c; base += 32) {
        int m = min(32, c - base);
        unsigned u = (lane < m) ? g_edata[s + base + lane] : 0u;
        int j = 0;
        for (; j + 4 <= m; j += 4) {
            unsigned u0 = __shfl_sync(0xffffffffu, u, j);
            unsigned u1 = __shfl_sync(0xffffffffu, u, j + 1);
            unsigned u2 = __shfl_sync(0xffffffffu, u, j + 2);
            unsigned u3 = __shfl_sync(0xffffffffu, u, j + 3);
            float2 v0 = ((const float2*)(g_y + (size_t)u0 * D))[lane];
            float2 v1 = ((const float2*)(g_y + (size_t)u1 * D))[lane];
            float2 v2 = ((const float2*)(g_y + (size_t)u2 * D))[lane];
            float2 v3 = ((const float2*)(g_y + (size_t)u3 * D))[lane];
            vx = fmaxf(vx, fmaxf(fmaxf(v0.x, v1.x), fmaxf(v2.x, v3.x)));
            vy = fmaxf(vy, fmaxf(fmaxf(v0.y, v1.y), fmaxf(v2.y, v3.y)));
        }
        for (; j < m; j++) {
            unsigned uu = __shfl_sync(0xffffffffu, u, j);
            float2 v = ((const float2*)(g_y + (size_t)uu * D))[lane];
            vx = fmaxf(vx, v.x);
            vy = fmaxf(vy, v.y);
        }
    }
    if (c == 0) { vx = 0.f; vy = 0.f; }
    float2 o; o.x = vx; o.y = vy;
    ((float2*)out)[(size_t)node * 32 + lane] = o;
}

// ---------------------------------------------------------------------------
extern "C" void kernel_launch(void* const* d_in, const int* in_sizes, int n_in,
                              void* d_out, int out_size) {
    const float* x    = (const float*)d_in[0];
    const float* W    = (const float*)d_in[1];
    const float* b    = (const float*)d_in[2];
    const int*   ei   = (const int*)d_in[3];
    const int*   attr = (const int*)d_in[4];
    float*       out  = (float*)d_out;

    int n = in_sizes[0] / D;
    int e = in_sizes[4];
    if (n > MAXN) n = MAXN;
    if (e > MAXE) e = MAXE;

    zero_cnt_kernel<<<(n + 255) / 256, 256>>>(n);
    gemm_kernel<<<1024, 128>>>(x, W, b, n);

    int et = (e + 3) / 4;
    hist_kernel<<<(et + 255) / 256, 256>>>(ei, e, n);

    int nb = (n + 1023) / 1024;
    scan1_kernel<<<nb, 1024>>>(n);
    scan2_kernel<<<1, 256>>>(nb);
    scan3_kernel<<<(n + 255) / 256, 256>>>(n);

    place_kernel<<<(et + 255) / 256, 256>>>(ei, attr, e, n);
    agg_kernel<<<(n * 32 + 255) / 256, 256>>>(out, n);
}